// round 2
// baseline (speedup 1.0000x reference)
#include <cuda_runtime.h>
#include <cuda_bf16.h>

// Problem constants
#define NN 10000
#define EE 128000
#define CC 128
#define AA 10
#define FF 8
// msg per node: C * (1+3+5) = 1152, layout per node: [l][m][c] blocks:
//   l=0: off 0 (128), l=1: off 128 (3*128), l=2: off 512 (5*128)
#define MSGW 1152
#define OUTR_ELEMS (NN * CC * 9)     // 11,520,000

// ---------------- scratch (device globals; no allocation allowed) ----------
__device__ float g_h[NN * CC];                 // 5.1 MB
__device__ float g_tpw[(long)EE * 384];        // 196.6 MB
__device__ float g_msg_r[NN * MSGW];           // 46 MB
__device__ float g_msg_i[NN * MSGW];           // 46 MB

__device__ __forceinline__ float silu(float x) {
    return x * (1.0f / (1.0f + __expf(-x)));
}

// ---------------- zero msg buffers -----------------------------------------
__global__ void k_zero() {
    int i = (blockIdx.x * 256 + threadIdx.x) * 4;
    if (i < NN * MSGW) {
        float4 z = make_float4(0.f, 0.f, 0.f, 0.f);
        *(float4*)(g_msg_r + i) = z;
        *(float4*)(g_msg_i + i) = z;
    }
}

// ---------------- h = node_feats @ W_up  (32 nodes / block) ----------------
#define H_SMEM ((128 * 128 + 32 * 128) * 4)
__global__ __launch_bounds__(256) void k_h(const float* __restrict__ feats,
                                           const float* __restrict__ Wup) {
    extern __shared__ float sm[];
    float* sW = sm;            // 128*128
    float* sF = sm + 16384;    // 32*128
    int n0 = blockIdx.x * 32;
    int t = threadIdx.x;
    for (int i = t; i < 16384; i += 256) sW[i] = Wup[i];
    for (int i = t; i < 4096; i += 256) {
        int n = n0 + (i >> 7);
        sF[i] = (n < NN) ? feats[n * CC + (i & 127)] : 0.f;
    }
    __syncthreads();
    int tk = (t & 31) * 4;
    int tn = (t >> 5) * 4;
    float acc[4][4] = {};
    for (int u = 0; u < 128; u++) {
        float4 b = *(const float4*)&sW[u * 128 + tk];
        #pragma unroll
        for (int i = 0; i < 4; i++) {
            float a = sF[(tn + i) * 128 + u];
            acc[i][0] = fmaf(a, b.x, acc[i][0]);
            acc[i][1] = fmaf(a, b.y, acc[i][1]);
            acc[i][2] = fmaf(a, b.z, acc[i][2]);
            acc[i][3] = fmaf(a, b.w, acc[i][3]);
        }
    }
    #pragma unroll
    for (int i = 0; i < 4; i++) {
        int n = n0 + tn + i;
        if (n < NN) {
            float4 v = make_float4(acc[i][0], acc[i][1], acc[i][2], acc[i][3]);
            *(float4*)&g_h[n * CC + tk] = v;
        }
    }
}

// ---------------- sc = einsum('nu,nv,uvk->nk') -----------------------------
// GEMM: X[n, u*10+v] = feats[n,u]*attrs[n,v]  (K=1280), W flat (1280,128)
#define SC_SMEM ((32 * 128 + 320 + 32 * 80 + 80 * 128) * 4)
__global__ __launch_bounds__(256) void k_sc(const float* __restrict__ feats,
                                            const float* __restrict__ attrs,
                                            const float* __restrict__ Wskip,
                                            float* __restrict__ sc_out) {
    extern __shared__ float sm[];
    float* sF = sm;              // 4096
    float* sA = sF + 4096;       // 320
    float* sX = sA + 320;        // 2560
    float* sW = sX + 2560;       // 10240
    int n0 = blockIdx.x * 32;
    int t = threadIdx.x;
    for (int i = t; i < 4096; i += 256) {
        int n = n0 + (i >> 7);
        sF[i] = (n < NN) ? feats[n * CC + (i & 127)] : 0.f;
    }
    for (int i = t; i < 320; i += 256) {
        int n = n0 + i / 10;
        sA[i] = (n < NN) ? attrs[n * AA + i % 10] : 0.f;
    }
    int tk = (t & 31) * 4;
    int tn = (t >> 5) * 4;
    float acc[4][4] = {};
    for (int uc = 0; uc < 16; uc++) {
        __syncthreads();
        for (int i = t; i < 10240; i += 256) sW[i] = Wskip[uc * 10240 + i];
        for (int idx = t; idx < 2560; idx += 256) {
            int n = idx / 80, i = idx % 80;
            sX[idx] = sF[n * 128 + uc * 8 + i / 10] * sA[n * 10 + i % 10];
        }
        __syncthreads();
        for (int i = 0; i < 80; i++) {
            float4 b = *(const float4*)&sW[i * 128 + tk];
            #pragma unroll
            for (int ii = 0; ii < 4; ii++) {
                float a = sX[(tn + ii) * 80 + i];
                acc[ii][0] = fmaf(a, b.x, acc[ii][0]);
                acc[ii][1] = fmaf(a, b.y, acc[ii][1]);
                acc[ii][2] = fmaf(a, b.z, acc[ii][2]);
                acc[ii][3] = fmaf(a, b.w, acc[ii][3]);
            }
        }
    }
    #pragma unroll
    for (int ii = 0; ii < 4; ii++) {
        int n = n0 + tn + ii;
        if (n < NN) {
            float4 v = make_float4(acc[ii][0], acc[ii][1], acc[ii][2], acc[ii][3]);
            *(float4*)&sc_out[n * CC + tk] = v;
        }
    }
}

// ---------------- fused edge MLP: 8->64->64->64->384 (silu x3) -------------
// 64 edges / block, all weights in smem.
#define MLP_SMEM ((512 + 4096 + 4096 + 24576 + 512 + 4096 + 4096) * 4)
__global__ __launch_bounds__(256) void k_mlp(const float* __restrict__ ef,
                                             const float* __restrict__ W1,
                                             const float* __restrict__ W2,
                                             const float* __restrict__ W3,
                                             const float* __restrict__ W4) {
    extern __shared__ float sm[];
    float* sW1 = sm;               // 512
    float* sW2 = sW1 + 512;        // 4096
    float* sW3 = sW2 + 4096;       // 4096
    float* sW4 = sW3 + 4096;       // 24576
    float* sEF = sW4 + 24576;      // 512
    float* sTA = sEF + 512;        // 4096
    float* sTB = sTA + 4096;       // 4096
    int t = threadIdx.x;
    for (int i = t; i < 512; i += 256) sW1[i] = W1[i];
    for (int i = t; i < 4096; i += 256) sW2[i] = W2[i];
    for (int i = t; i < 4096; i += 256) sW3[i] = W3[i];
    for (int i = t; i < 24576; i += 256) sW4[i] = W4[i];
    int e0 = blockIdx.x * 64;  // EE % 64 == 0, no guards
    for (int i = t; i < 512; i += 256) sEF[i] = ef[e0 * FF + i];
    __syncthreads();
    // layer 1
    for (int o = t; o < 4096; o += 256) {
        int e = o >> 6, j = o & 63;
        float acc = 0.f;
        #pragma unroll
        for (int f = 0; f < 8; f++) acc = fmaf(sEF[e * 8 + f], sW1[f * 64 + j], acc);
        sTA[o] = silu(acc);
    }
    __syncthreads();
    // layer 2: sTB = silu(sTA @ W2)
    {
        int j0 = (t & 15) * 4, el = (t >> 4) * 4;
        float acc[4][4] = {};
        for (int u = 0; u < 64; u++) {
            float4 b = *(const float4*)&sW2[u * 64 + j0];
            #pragma unroll
            for (int i = 0; i < 4; i++) {
                float a = sTA[(el + i) * 64 + u];
                acc[i][0] = fmaf(a, b.x, acc[i][0]);
                acc[i][1] = fmaf(a, b.y, acc[i][1]);
                acc[i][2] = fmaf(a, b.z, acc[i][2]);
                acc[i][3] = fmaf(a, b.w, acc[i][3]);
            }
        }
        #pragma unroll
        for (int i = 0; i < 4; i++)
            #pragma unroll
            for (int j = 0; j < 4; j++) sTB[(el + i) * 64 + j0 + j] = silu(acc[i][j]);
    }
    __syncthreads();
    // layer 3: sTA = silu(sTB @ W3)
    {
        int j0 = (t & 15) * 4, el = (t >> 4) * 4;
        float acc[4][4] = {};
        for (int u = 0; u < 64; u++) {
            float4 b = *(const float4*)&sW3[u * 64 + j0];
            #pragma unroll
            for (int i = 0; i < 4; i++) {
                float a = sTB[(el + i) * 64 + u];
                acc[i][0] = fmaf(a, b.x, acc[i][0]);
                acc[i][1] = fmaf(a, b.y, acc[i][1]);
                acc[i][2] = fmaf(a, b.z, acc[i][2]);
                acc[i][3] = fmaf(a, b.w, acc[i][3]);
            }
        }
        #pragma unroll
        for (int i = 0; i < 4; i++)
            #pragma unroll
            for (int j = 0; j < 4; j++) sTA[(el + i) * 64 + j0 + j] = silu(acc[i][j]);
    }
    __syncthreads();
    // layer 4: tpw = sTA @ W4  (64x384), write to global
    for (int rep = 0; rep < 6; rep++) {
        int tile = rep * 256 + t;
        int et = tile / 96, jt = tile % 96;
        int el = et * 4, j0 = jt * 4;
        float acc[4][4] = {};
        for (int u = 0; u < 64; u++) {
            float4 b = *(const float4*)&sW4[u * 384 + j0];
            #pragma unroll
            for (int i = 0; i < 4; i++) {
                float a = sTA[(el + i) * 64 + u];
                acc[i][0] = fmaf(a, b.x, acc[i][0]);
                acc[i][1] = fmaf(a, b.y, acc[i][1]);
                acc[i][2] = fmaf(a, b.z, acc[i][2]);
                acc[i][3] = fmaf(a, b.w, acc[i][3]);
            }
        }
        #pragma unroll
        for (int i = 0; i < 4; i++) {
            float4 v = make_float4(acc[i][0], acc[i][1], acc[i][2], acc[i][3]);
            *(float4*)&g_tpw[(long)(e0 + el + i) * 384 + j0] = v;
        }
    }
}

// ---------------- conv_tp + atomic segment_sum -----------------------------
// 2 edges / block of 256. thread c handles channel c.
__global__ __launch_bounds__(256) void k_conv(const int* __restrict__ eidx,
                                              const float* __restrict__ yr,
                                              const float* __restrict__ yi) {
    int e = blockIdx.x * 2 + (threadIdx.x >> 7);
    int c = threadIdx.x & 127;
    int s = eidx[e];
    int r = eidx[EE + e];
    float x = g_h[s * CC + c];
    const float* tw = g_tpw + (long)e * 384;
    float xw0 = x * tw[c];
    float xw1 = x * tw[128 + c];
    float xw2 = x * tw[256 + c];
    const float* yre = yr + e * 9;
    const float* yie = yi + e * 9;
    float* mr = g_msg_r + r * MSGW + c;
    float* mi = g_msg_i + r * MSGW + c;
    atomicAdd(mr, xw0 * yre[0]);
    atomicAdd(mi, xw0 * yie[0]);
    #pragma unroll
    for (int m = 0; m < 3; m++) {
        atomicAdd(mr + 128 + m * 128, xw1 * yre[1 + m]);
        atomicAdd(mi + 128 + m * 128, xw1 * yie[1 + m]);
    }
    #pragma unroll
    for (int m = 0; m < 5; m++) {
        atomicAdd(mr + 512 + m * 128, xw2 * yre[4 + m]);
        atomicAdd(mi + 512 + m * 128, xw2 * yie[4 + m]);
    }
}

// ---------------- linear_irreps: out[n,k,m] = sum_u msg[n,l,m,u] W_l[u,k] --
// rows = (n,m) pairs, contiguous-128 in msg. 32 rows x 128 k per block.
// (Round 1 bug: block loaded 64 rows but compute tiling only covers 32 ->
//  half the output rows never written. Now 32 rows/block, grid doubled.)
#define LIN_SMEM ((128 * 128 + 32 * 128) * 4)
__global__ __launch_bounds__(256) void k_linear(int use_imag,
                                                const float* __restrict__ W,
                                                float* __restrict__ out,
                                                int d, int loff, int moff) {
    extern __shared__ float sm[];
    float* sW = sm;              // 16384
    float* sA = sm + 16384;      // 4096 (32 rows x 128)
    const float* msg = use_imag ? g_msg_i : g_msg_r;
    int r0 = blockIdx.x * 32;
    int nrows = NN * d;
    int t = threadIdx.x;
    for (int i = t; i < 16384; i += 256) sW[i] = W[i];
    for (int i = t; i < 4096; i += 256) {
        int rl = i >> 7, u = i & 127;
        int row = r0 + rl;
        float v = 0.f;
        if (row < nrows) {
            int n = row / d, m = row % d;
            v = msg[n * MSGW + loff + m * 128 + u];
        }
        sA[i] = v;
    }
    __syncthreads();
    int tk = (t & 31) * 4;
    int tr = (t >> 5) * 4;
    float acc[4][4] = {};
    for (int u = 0; u < 128; u++) {
        float4 b = *(const float4*)&sW[u * 128 + tk];
        #pragma unroll
        for (int i = 0; i < 4; i++) {
            float a = sA[(tr + i) * 128 + u];
            acc[i][0] = fmaf(a, b.x, acc[i][0]);
            acc[i][1] = fmaf(a, b.y, acc[i][1]);
            acc[i][2] = fmaf(a, b.z, acc[i][2]);
            acc[i][3] = fmaf(a, b.w, acc[i][3]);
        }
    }
    #pragma unroll
    for (int i = 0; i < 4; i++) {
        int row = r0 + tr + i;
        if (row < nrows) {
            int n = row / d, m = row % d;
            float* o = out + n * MSGW + moff + m;
            #pragma unroll
            for (int j = 0; j < 4; j++) o[(tk + j) * 9] = acc[i][j];
        }
    }
}

// ---------------- launch ---------------------------------------------------
extern "C" void kernel_launch(void* const* d_in, const int* in_sizes, int n_in,
                              void* d_out, int out_size) {
    const float* node_attrs = (const float*)d_in[0];
    const float* node_feats = (const float*)d_in[1];
    const float* yr        = (const float*)d_in[2];
    const float* yi        = (const float*)d_in[3];
    const float* ef        = (const float*)d_in[4];
    const int*   eidx      = (const int*)  d_in[5];
    const float* Wup       = (const float*)d_in[6];
    const float* Wskip     = (const float*)d_in[7];
    const float* W1        = (const float*)d_in[8];
    const float* W2        = (const float*)d_in[9];
    const float* W3        = (const float*)d_in[10];
    const float* W4        = (const float*)d_in[11];
    const float* Wl0       = (const float*)d_in[12];
    const float* Wl1       = (const float*)d_in[13];
    const float* Wl2       = (const float*)d_in[14];

    float* out   = (float*)d_out;
    float* out_r = out;
    float* out_i = out + OUTR_ELEMS;
    float* out_s = out + 2 * OUTR_ELEMS;

    cudaFuncSetAttribute(k_h,      cudaFuncAttributeMaxDynamicSharedMemorySize, H_SMEM);
    cudaFuncSetAttribute(k_sc,     cudaFuncAttributeMaxDynamicSharedMemorySize, SC_SMEM);
    cudaFuncSetAttribute(k_mlp,    cudaFuncAttributeMaxDynamicSharedMemorySize, MLP_SMEM);
    cudaFuncSetAttribute(k_linear, cudaFuncAttributeMaxDynamicSharedMemorySize, LIN_SMEM);

    k_zero<<<(NN * MSGW) / 4 / 256, 256>>>();
    k_h<<<(NN + 31) / 32, 256, H_SMEM>>>(node_feats, Wup);
    k_sc<<<(NN + 31) / 32, 256, SC_SMEM>>>(node_feats, node_attrs, Wskip, out_s);
    k_mlp<<<EE / 64, 256, MLP_SMEM>>>(ef, W1, W2, W3, W4);
    k_conv<<<EE / 2, 256>>>(eidx, yr, yi);

    // linear_irreps: (use_imag, W, out, d, loff_in_msg, moff_in_out)
    k_linear<<<(NN * 1 + 31) / 32, 256, LIN_SMEM>>>(0, Wl0, out_r, 1, 0,   0);
    k_linear<<<(NN * 3 + 31) / 32, 256, LIN_SMEM>>>(0, Wl1, out_r, 3, 128, 1);
    k_linear<<<(NN * 5 + 31) / 32, 256, LIN_SMEM>>>(0, Wl2, out_r, 5, 512, 4);
    k_linear<<<(NN * 1 + 31) / 32, 256, LIN_SMEM>>>(1, Wl0, out_i, 1, 0,   0);
    k_linear<<<(NN * 3 + 31) / 32, 256, LIN_SMEM>>>(1, Wl1, out_i, 3, 128, 1);
    k_linear<<<(NN * 5 + 31) / 32, 256, LIN_SMEM>>>(1, Wl2, out_i, 5, 512, 4);
}

// round 3
// speedup vs baseline: 1.3034x; 1.3034x over previous
#include <cuda_runtime.h>
#include <cuda_bf16.h>

// Problem constants
#define NN 10000
#define EE 128000
#define CC 128
#define AA 10
#define FF 8
#define MSGW 1152
#define OUTR_ELEMS (NN * CC * 9)

// ---------------- scratch (device globals) ---------------------------------
__device__ float g_h[NN * CC];
__device__ float g_tpw[(long)EE * 384];
__device__ float g_msg_r[NN * MSGW];
__device__ float g_msg_i[NN * MSGW];
__device__ int   g_deg[NN];
__device__ int   g_cur[NN];
__device__ int   g_off[NN + 1];
__device__ int   g_elist[EE];

__device__ __forceinline__ float silu(float x) {
    return x * (1.0f / (1.0f + __expf(-x)));
}

// f32x2 packed helpers (sm_100+)
__device__ __forceinline__ unsigned long long pack2(float lo, float hi) {
    unsigned long long r;
    asm("mov.b64 %0, {%1, %2};" : "=l"(r) : "f"(lo), "f"(hi));
    return r;
}
__device__ __forceinline__ void unpack2(unsigned long long v, float& lo, float& hi) {
    asm("mov.b64 {%0, %1}, %2;" : "=f"(lo), "=f"(hi) : "l"(v));
}
__device__ __forceinline__ void ffma2(unsigned long long& acc,
                                      unsigned long long a, unsigned long long b) {
    asm("fma.rn.f32x2 %0, %1, %2, %0;" : "+l"(acc) : "l"(a), "l"(b));
}

// ---------------- CSR build -------------------------------------------------
__global__ void k_reset() {
    int t = blockIdx.x * 256 + threadIdx.x;
    if (t < NN) { g_deg[t] = 0; g_cur[t] = 0; }
}
__global__ void k_count(const int* __restrict__ eidx) {
    int e = blockIdx.x * 256 + threadIdx.x;
    if (e < EE) atomicAdd(&g_deg[eidx[EE + e]], 1);
}
__global__ void k_scan() {  // single block, 1024 threads; NN = 1000*10
    __shared__ int part[1024];
    int t = threadIdx.x;
    int base = t * 10;
    int s = 0;
    if (t < 1000)
        for (int i = 0; i < 10; i++) s += g_deg[base + i];
    part[t] = s;
    __syncthreads();
    for (int d = 1; d < 1024; d <<= 1) {
        int v = (t >= d) ? part[t - d] : 0;
        __syncthreads();
        part[t] += v;
        __syncthreads();
    }
    int excl = (t == 0) ? 0 : part[t - 1];
    if (t < 1000) {
        int run = excl;
        for (int i = 0; i < 10; i++) { g_off[base + i] = run; run += g_deg[base + i]; }
        if (t == 999) g_off[NN] = run;
    }
}
__global__ void k_fill(const int* __restrict__ eidx) {
    int e = blockIdx.x * 256 + threadIdx.x;
    if (e < EE) {
        int r = eidx[EE + e];
        int pos = atomicAdd(&g_cur[r], 1);
        g_elist[g_off[r] + pos] = e;
    }
}

// ---------------- h = node_feats @ W_up ------------------------------------
#define H_SMEM ((128 * 128 + 32 * 128) * 4)
__global__ __launch_bounds__(256) void k_h(const float* __restrict__ feats,
                                           const float* __restrict__ Wup) {
    extern __shared__ float sm[];
    float* sW = sm;
    float* sF = sm + 16384;
    int n0 = blockIdx.x * 32;
    int t = threadIdx.x;
    for (int i = t; i < 16384; i += 256) sW[i] = Wup[i];
    for (int i = t; i < 4096; i += 256) {
        int n = n0 + (i >> 7);
        sF[i] = (n < NN) ? feats[n * CC + (i & 127)] : 0.f;
    }
    __syncthreads();
    int tk = (t & 31) * 4;
    int tn = (t >> 5) * 4;
    float acc[4][4] = {};
    for (int u = 0; u < 128; u++) {
        float4 b = *(const float4*)&sW[u * 128 + tk];
        #pragma unroll
        for (int i = 0; i < 4; i++) {
            float a = sF[(tn + i) * 128 + u];
            acc[i][0] = fmaf(a, b.x, acc[i][0]);
            acc[i][1] = fmaf(a, b.y, acc[i][1]);
            acc[i][2] = fmaf(a, b.z, acc[i][2]);
            acc[i][3] = fmaf(a, b.w, acc[i][3]);
        }
    }
    #pragma unroll
    for (int i = 0; i < 4; i++) {
        int n = n0 + tn + i;
        if (n < NN) {
            float4 v = make_float4(acc[i][0], acc[i][1], acc[i][2], acc[i][3]);
            *(float4*)&g_h[n * CC + tk] = v;
        }
    }
}

// ---------------- sc --------------------------------------------------------
#define SC_SMEM ((32 * 128 + 320 + 32 * 80 + 80 * 128) * 4)
__global__ __launch_bounds__(256) void k_sc(const float* __restrict__ feats,
                                            const float* __restrict__ attrs,
                                            const float* __restrict__ Wskip,
                                            float* __restrict__ sc_out) {
    extern __shared__ float sm[];
    float* sF = sm;
    float* sA = sF + 4096;
    float* sX = sA + 320;
    float* sW = sX + 2560;
    int n0 = blockIdx.x * 32;
    int t = threadIdx.x;
    for (int i = t; i < 4096; i += 256) {
        int n = n0 + (i >> 7);
        sF[i] = (n < NN) ? feats[n * CC + (i & 127)] : 0.f;
    }
    for (int i = t; i < 320; i += 256) {
        int n = n0 + i / 10;
        sA[i] = (n < NN) ? attrs[n * AA + i % 10] : 0.f;
    }
    int tk = (t & 31) * 4;
    int tn = (t >> 5) * 4;
    float acc[4][4] = {};
    for (int uc = 0; uc < 16; uc++) {
        __syncthreads();
        for (int i = t; i < 10240; i += 256) sW[i] = Wskip[uc * 10240 + i];
        for (int idx = t; idx < 2560; idx += 256) {
            int n = idx / 80, i = idx % 80;
            sX[idx] = sF[n * 128 + uc * 8 + i / 10] * sA[n * 10 + i % 10];
        }
        __syncthreads();
        for (int i = 0; i < 80; i++) {
            float4 b = *(const float4*)&sW[i * 128 + tk];
            #pragma unroll
            for (int ii = 0; ii < 4; ii++) {
                float a = sX[(tn + ii) * 80 + i];
                acc[ii][0] = fmaf(a, b.x, acc[ii][0]);
                acc[ii][1] = fmaf(a, b.y, acc[ii][1]);
                acc[ii][2] = fmaf(a, b.z, acc[ii][2]);
                acc[ii][3] = fmaf(a, b.w, acc[ii][3]);
            }
        }
    }
    #pragma unroll
    for (int ii = 0; ii < 4; ii++) {
        int n = n0 + tn + ii;
        if (n < NN) {
            float4 v = make_float4(acc[ii][0], acc[ii][1], acc[ii][2], acc[ii][3]);
            *(float4*)&sc_out[n * CC + tk] = v;
        }
    }
}

// ---------------- fused edge MLP (persistent, transposed, f32x2) -----------
// 512 threads, 128 edges / tile, activations stored [j][e] (edge-major vecs).
// smem floats: W1 512 | W2 4096 | W3 4096 | W4 24576 | EFt 1024 | TA 8192 | TB 8192
#define MLP_NF (512 + 4096 + 4096 + 24576 + 1024 + 8192 + 8192)
#define MLP_SMEM (MLP_NF * 4)
__global__ __launch_bounds__(512) void k_mlp(const float* __restrict__ ef,
                                             const float* __restrict__ W1,
                                             const float* __restrict__ W2,
                                             const float* __restrict__ W3,
                                             const float* __restrict__ W4) {
    extern __shared__ float sm[];
    float* sW1  = sm;
    float* sW2  = sW1 + 512;
    float* sW3  = sW2 + 4096;
    float* sW4  = sW3 + 4096;
    float* sEFt = sW4 + 24576;   // [f][e]  8 x 128
    float* sTA  = sEFt + 1024;   // [j][e] 64 x 128
    float* sTB  = sTA + 8192;    // [j][e] 64 x 128
    int t = threadIdx.x;
    for (int i = t; i < 512; i += 512) sW1[i] = W1[i];
    for (int i = t; i < 4096; i += 512) sW2[i] = W2[i];
    for (int i = t; i < 4096; i += 512) sW3[i] = W3[i];
    for (int i = t; i < 24576; i += 512) sW4[i] = W4[i];

    int j0c = (t & 15) * 4;        // layer2/3 j tile
    int elc = (t >> 4) * 4;        // layer2/3 edge tile (0..31 groups)

    for (int tile = blockIdx.x; tile < EE / 128; tile += gridDim.x) {
        int e0 = tile * 128;
        __syncthreads();  // protect smem reuse across tiles
        // load edge feats transposed: sEFt[f][e]
        for (int i = t; i < 1024; i += 512) {
            int e = i >> 3, f = i & 7;
            sEFt[f * 128 + e] = ef[(e0 + e) * FF + f];
        }
        __syncthreads();
        // layer 1: sTA[j][e] = silu(sum_f EF[e][f] W1[f][j])
        for (int o = t; o < 8192; o += 512) {
            int j = o >> 7, e = o & 127;
            float acc = 0.f;
            #pragma unroll
            for (int f = 0; f < 8; f++) acc = fmaf(sEFt[f * 128 + e], sW1[f * 64 + j], acc);
            sTA[j * 128 + e] = silu(acc);
        }
        __syncthreads();
        // layer 2: sTB[j][e] = silu(sum_u TA[u][e] W2[u][j])   (f32x2 over e)
        {
            unsigned long long acc[2][4] = {};
            for (int u = 0; u < 64; u++) {
                ulonglong2 a = *(const ulonglong2*)&sTA[u * 128 + elc];
                float4 w = *(const float4*)&sW2[u * 64 + j0c];
                unsigned long long w0 = pack2(w.x, w.x), w1 = pack2(w.y, w.y);
                unsigned long long w2 = pack2(w.z, w.z), w3 = pack2(w.w, w.w);
                ffma2(acc[0][0], a.x, w0); ffma2(acc[1][0], a.y, w0);
                ffma2(acc[0][1], a.x, w1); ffma2(acc[1][1], a.y, w1);
                ffma2(acc[0][2], a.x, w2); ffma2(acc[1][2], a.y, w2);
                ffma2(acc[0][3], a.x, w3); ffma2(acc[1][3], a.y, w3);
            }
            #pragma unroll
            for (int jj = 0; jj < 4; jj++) {
                float f0, f1, f2, f3;
                unpack2(acc[0][jj], f0, f1);
                unpack2(acc[1][jj], f2, f3);
                float4 v = make_float4(silu(f0), silu(f1), silu(f2), silu(f3));
                *(float4*)&sTB[(j0c + jj) * 128 + elc] = v;
            }
        }
        __syncthreads();
        // layer 3: sTA[j][e] = silu(sum_u TB[u][e] W3[u][j])
        {
            unsigned long long acc[2][4] = {};
            for (int u = 0; u < 64; u++) {
                ulonglong2 a = *(const ulonglong2*)&sTB[u * 128 + elc];
                float4 w = *(const float4*)&sW3[u * 64 + j0c];
                unsigned long long w0 = pack2(w.x, w.x), w1 = pack2(w.y, w.y);
                unsigned long long w2 = pack2(w.z, w.z), w3 = pack2(w.w, w.w);
                ffma2(acc[0][0], a.x, w0); ffma2(acc[1][0], a.y, w0);
                ffma2(acc[0][1], a.x, w1); ffma2(acc[1][1], a.y, w1);
                ffma2(acc[0][2], a.x, w2); ffma2(acc[1][2], a.y, w2);
                ffma2(acc[0][3], a.x, w3); ffma2(acc[1][3], a.y, w3);
            }
            #pragma unroll
            for (int jj = 0; jj < 4; jj++) {
                float f0, f1, f2, f3;
                unpack2(acc[0][jj], f0, f1);
                unpack2(acc[1][jj], f2, f3);
                float4 v = make_float4(silu(f0), silu(f1), silu(f2), silu(f3));
                *(float4*)&sTA[(j0c + jj) * 128 + elc] = v;
            }
        }
        __syncthreads();
        // layer 4: tpw[e][j] = sum_u TA[u][e] W4[u][j]  (128e x 384j, 6 reps)
        for (int rep = 0; rep < 6; rep++) {
            int tl = rep * 512 + t;
            int jt = tl % 96, et = tl / 96;   // et 0..31
            int j0 = jt * 4, el = et * 4;
            unsigned long long acc[2][4] = {};
            for (int u = 0; u < 64; u++) {
                ulonglong2 a = *(const ulonglong2*)&sTA[u * 128 + el];
                float4 w = *(const float4*)&sW4[u * 384 + j0];
                unsigned long long w0 = pack2(w.x, w.x), w1 = pack2(w.y, w.y);
                unsigned long long w2 = pack2(w.z, w.z), w3 = pack2(w.w, w.w);
                ffma2(acc[0][0], a.x, w0); ffma2(acc[1][0], a.y, w0);
                ffma2(acc[0][1], a.x, w1); ffma2(acc[1][1], a.y, w1);
                ffma2(acc[0][2], a.x, w2); ffma2(acc[1][2], a.y, w2);
                ffma2(acc[0][3], a.x, w3); ffma2(acc[1][3], a.y, w3);
            }
            float f[4][4];
            #pragma unroll
            for (int jj = 0; jj < 4; jj++) {
                unpack2(acc[0][jj], f[0][jj], f[1][jj]);
                unpack2(acc[1][jj], f[2][jj], f[3][jj]);
            }
            #pragma unroll
            for (int ee = 0; ee < 4; ee++) {
                float4 v = make_float4(f[ee][0], f[ee][1], f[ee][2], f[ee][3]);
                *(float4*)&g_tpw[(long)(e0 + el + ee) * 384 + j0] = v;
            }
        }
    }
}

// ---------------- gather conv_tp + segment_sum (no float atomics) ----------
// 1 warp per node, 4 channels/thread. 8 nodes / 256-thread block.
__global__ __launch_bounds__(256) void k_gather(const int* __restrict__ eidx,
                                                const float* __restrict__ yr,
                                                const float* __restrict__ yi) {
    int t = threadIdx.x;
    int n = blockIdx.x * 8 + (t >> 5);
    int c0 = (t & 31) * 4;
    float4 ar[9], ai[9];
    #pragma unroll
    for (int m = 0; m < 9; m++) {
        ar[m] = make_float4(0.f, 0.f, 0.f, 0.f);
        ai[m] = make_float4(0.f, 0.f, 0.f, 0.f);
    }
    int beg = g_off[n], end = g_off[n + 1];
    for (int i = beg; i < end; i++) {
        int e = g_elist[i];
        int s = eidx[e];
        float4 x  = *(const float4*)&g_h[s * CC + c0];
        const float* tw = g_tpw + (long)e * 384;
        float4 t0 = *(const float4*)&tw[c0];
        float4 t1 = *(const float4*)&tw[128 + c0];
        float4 t2 = *(const float4*)&tw[256 + c0];
        float4 xw0 = make_float4(x.x * t0.x, x.y * t0.y, x.z * t0.z, x.w * t0.w);
        float4 xw1 = make_float4(x.x * t1.x, x.y * t1.y, x.z * t1.z, x.w * t1.w);
        float4 xw2 = make_float4(x.x * t2.x, x.y * t2.y, x.z * t2.z, x.w * t2.w);
        const float* yre = yr + e * 9;
        const float* yie = yi + e * 9;
        #pragma unroll
        for (int m = 0; m < 9; m++) {
            float4 xw = (m == 0) ? xw0 : (m < 4) ? xw1 : xw2;
            float vr = yre[m], vi = yie[m];
            ar[m].x = fmaf(xw.x, vr, ar[m].x); ar[m].y = fmaf(xw.y, vr, ar[m].y);
            ar[m].z = fmaf(xw.z, vr, ar[m].z); ar[m].w = fmaf(xw.w, vr, ar[m].w);
            ai[m].x = fmaf(xw.x, vi, ai[m].x); ai[m].y = fmaf(xw.y, vi, ai[m].y);
            ai[m].z = fmaf(xw.z, vi, ai[m].z); ai[m].w = fmaf(xw.w, vi, ai[m].w);
        }
    }
    // msg layout per node: l0 @0 (m=0), l1 @128 (m=1..3), l2 @512 (m=4..8)
    float* mr = g_msg_r + n * MSGW;
    float* mi = g_msg_i + n * MSGW;
    *(float4*)&mr[c0] = ar[0];
    *(float4*)&mi[c0] = ai[0];
    #pragma unroll
    for (int m = 0; m < 3; m++) {
        *(float4*)&mr[128 + m * 128 + c0] = ar[1 + m];
        *(float4*)&mi[128 + m * 128 + c0] = ai[1 + m];
    }
    #pragma unroll
    for (int m = 0; m < 5; m++) {
        *(float4*)&mr[512 + m * 128 + c0] = ar[4 + m];
        *(float4*)&mi[512 + m * 128 + c0] = ai[4 + m];
    }
}

// ---------------- linear_irreps (persistent; W loaded once per block) ------
#define LIN_SMEM ((128 * 128 + 32 * 128) * 4)
__global__ __launch_bounds__(256) void k_linear(int use_imag,
                                                const float* __restrict__ W,
                                                float* __restrict__ out,
                                                int d, int loff, int moff) {
    extern __shared__ float sm[];
    float* sW = sm;              // 16384
    float* sA = sm + 16384;      // 32 x 128
    const float* msg = use_imag ? g_msg_i : g_msg_r;
    int nrows = NN * d;
    int t = threadIdx.x;
    for (int i = t; i < 16384; i += 256) sW[i] = W[i];
    int tk = (t & 31) * 4;
    int tr = (t >> 5) * 4;
    for (int r0 = blockIdx.x * 32; r0 < nrows; r0 += gridDim.x * 32) {
        __syncthreads();  // protect sA reuse (also orders first-iter sW)
        for (int i = t; i < 4096; i += 256) {
            int rl = i >> 7, u = i & 127;
            int row = r0 + rl;
            float v = 0.f;
            if (row < nrows) {
                int n = row / d, m = row % d;
                v = msg[n * MSGW + loff + m * 128 + u];
            }
            sA[i] = v;
        }
        __syncthreads();
        float acc[4][4] = {};
        for (int u = 0; u < 128; u++) {
            float4 b = *(const float4*)&sW[u * 128 + tk];
            #pragma unroll
            for (int i = 0; i < 4; i++) {
                float a = sA[(tr + i) * 128 + u];
                acc[i][0] = fmaf(a, b.x, acc[i][0]);
                acc[i][1] = fmaf(a, b.y, acc[i][1]);
                acc[i][2] = fmaf(a, b.z, acc[i][2]);
                acc[i][3] = fmaf(a, b.w, acc[i][3]);
            }
        }
        #pragma unroll
        for (int i = 0; i < 4; i++) {
            int row = r0 + tr + i;
            if (row < nrows) {
                int n = row / d, m = row % d;
                float* o = out + n * MSGW + moff + m;
                #pragma unroll
                for (int j = 0; j < 4; j++) o[(tk + j) * 9] = acc[i][j];
            }
        }
    }
}

// ---------------- launch ---------------------------------------------------
extern "C" void kernel_launch(void* const* d_in, const int* in_sizes, int n_in,
                              void* d_out, int out_size) {
    const float* node_attrs = (const float*)d_in[0];
    const float* node_feats = (const float*)d_in[1];
    const float* yr        = (const float*)d_in[2];
    const float* yi        = (const float*)d_in[3];
    const float* ef        = (const float*)d_in[4];
    const int*   eidx      = (const int*)  d_in[5];
    const float* Wup       = (const float*)d_in[6];
    const float* Wskip     = (const float*)d_in[7];
    const float* W1        = (const float*)d_in[8];
    const float* W2        = (const float*)d_in[9];
    const float* W3        = (const float*)d_in[10];
    const float* W4        = (const float*)d_in[11];
    const float* Wl0       = (const float*)d_in[12];
    const float* Wl1       = (const float*)d_in[13];
    const float* Wl2       = (const float*)d_in[14];

    float* out   = (float*)d_out;
    float* out_r = out;
    float* out_i = out + OUTR_ELEMS;
    float* out_s = out + 2 * OUTR_ELEMS;

    cudaFuncSetAttribute(k_h,      cudaFuncAttributeMaxDynamicSharedMemorySize, H_SMEM);
    cudaFuncSetAttribute(k_sc,     cudaFuncAttributeMaxDynamicSharedMemorySize, SC_SMEM);
    cudaFuncSetAttribute(k_mlp,    cudaFuncAttributeMaxDynamicSharedMemorySize, MLP_SMEM);
    cudaFuncSetAttribute(k_linear, cudaFuncAttributeMaxDynamicSharedMemorySize, LIN_SMEM);

    // CSR build
    k_reset<<<(NN + 255) / 256, 256>>>();
    k_count<<<(EE + 255) / 256, 256>>>(eidx);
    k_scan<<<1, 1024>>>();
    k_fill<<<(EE + 255) / 256, 256>>>(eidx);

    k_h<<<(NN + 31) / 32, 256, H_SMEM>>>(node_feats, Wup);
    k_sc<<<(NN + 31) / 32, 256, SC_SMEM>>>(node_feats, node_attrs, Wskip, out_s);
    k_mlp<<<148, 512, MLP_SMEM>>>(ef, W1, W2, W3, W4);
    k_gather<<<NN / 8, 256>>>(eidx, yr, yi);

    k_linear<<<296, 256, LIN_SMEM>>>(0, Wl0, out_r, 1, 0,   0);
    k_linear<<<296, 256, LIN_SMEM>>>(0, Wl1, out_r, 3, 128, 1);
    k_linear<<<296, 256, LIN_SMEM>>>(0, Wl2, out_r, 5, 512, 4);
    k_linear<<<296, 256, LIN_SMEM>>>(1, Wl0, out_i, 1, 0,   0);
    k_linear<<<296, 256, LIN_SMEM>>>(1, Wl1, out_i, 3, 128, 1);
    k_linear<<<296, 256, LIN_SMEM>>>(1, Wl2, out_i, 5, 512, 4);
}